// round 1
// baseline (speedup 1.0000x reference)
#include <cuda_runtime.h>
#include <cuda_bf16.h>
#include <cstdint>

// Problem constants
#define M_TOK   32768          // B*NW*WIN tokens
#define C_DIM   512
#define N_TOT   1536           // 3 * 512 output channels (Q,K,V concat)
#define MAT_ELEMS 16777216     // 512 windows * 8 heads * 64 tok * 64 d

// scratch: Q,K,V in [win][head][tok][d] layout, fp32
__device__ float g_qkv[3u * MAT_ELEMS];

// ---------------- helpers ----------------
__device__ __forceinline__ uint32_t f2tf(float x) {
    uint32_t u;
    asm("cvt.rna.tf32.f32 %0, %1;" : "=r"(u) : "f"(x));
    return u;
}

__device__ __forceinline__ void mma_tf32(float c[4], const uint32_t a[4],
                                         uint32_t b0, uint32_t b1) {
    asm volatile(
        "mma.sync.aligned.m16n8k8.row.col.f32.tf32.tf32.f32 "
        "{%0,%1,%2,%3}, {%4,%5,%6,%7}, {%8,%9}, {%0,%1,%2,%3};"
        : "+f"(c[0]), "+f"(c[1]), "+f"(c[2]), "+f"(c[3])
        : "r"(a[0]), "r"(a[1]), "r"(a[2]), "r"(a[3]), "r"(b0), "r"(b1));
}

__device__ __forceinline__ void cpa16(void* s, const void* g) {
    uint32_t sa = (uint32_t)__cvta_generic_to_shared(s);
    asm volatile("cp.async.cg.shared.global [%0], [%1], 16;\n" :: "r"(sa), "l"(g));
}

// ---------------- Kernel 1: fused QKV GEMM ----------------
// C[m, n] = X[m, :] . W[n, :] + b[n],  W/b = concat(Wq,Wk,Wv)
// output scattered to g_qkv[mat][win][h][t][d]
#define BM 128
#define BN 128
#define BK 16
#define SSTR 20   // smem row stride in floats (16B-aligned rows)

__global__ void __launch_bounds__(256)
qkv_gemm(const float* __restrict__ X,
         const float* __restrict__ Wq, const float* __restrict__ bq,
         const float* __restrict__ Wk, const float* __restrict__ bk,
         const float* __restrict__ Wv, const float* __restrict__ bv)
{
    __shared__ float As[2][BM][SSTR];
    __shared__ float Bs[2][BN][SSTR];

    const int tid  = threadIdx.x;
    const int lane = tid & 31;
    const int warp = tid >> 5;
    const int wm   = (warp >> 2) * 64;   // 0 or 64
    const int wn   = (warp & 3) * 32;    // 0,32,64,96
    const int qr   = lane >> 2;          // 0..7
    const int qc   = lane & 3;           // 0..3

    const int bm0 = blockIdx.y * BM;
    const int bn0 = blockIdx.x * BN;
    const int mat = bn0 >> 9;            // 0,1,2 (BN=128 divides 512)
    const int nl0 = bn0 & 511;
    const float* __restrict__ W    = (mat == 0) ? Wq : (mat == 1) ? Wk : Wv;
    const float* __restrict__ bias = (mat == 0) ? bq : (mat == 1) ? bk : bv;

    float acc[4][4][4];
#pragma unroll
    for (int i = 0; i < 4; i++)
#pragma unroll
        for (int j = 0; j < 4; j++)
#pragma unroll
            for (int k = 0; k < 4; k++) acc[i][j][k] = 0.f;

    // stage loader: 512 float4 per matrix tile, 2 per thread
    auto stage_load = [&](int s, int kt) {
        const int k0 = kt * BK;
#pragma unroll
        for (int i = 0; i < 2; i++) {
            int idx = tid + i * 256;
            int r   = idx >> 2;
            int c4  = (idx & 3) * 4;
            cpa16(&As[s][r][c4], X + (size_t)(bm0 + r) * C_DIM + k0 + c4);
            cpa16(&Bs[s][r][c4], W + (size_t)(nl0 + r) * C_DIM + k0 + c4);
        }
        asm volatile("cp.async.commit_group;\n" ::: "memory");
    };

    stage_load(0, 0);

    const int NKT = C_DIM / BK;  // 32
    for (int kt = 0; kt < NKT; kt++) {
        if (kt + 1 < NKT) {
            stage_load((kt + 1) & 1, kt + 1);
            asm volatile("cp.async.wait_group 1;\n" ::: "memory");
        } else {
            asm volatile("cp.async.wait_group 0;\n" ::: "memory");
        }
        __syncthreads();

        const int s = kt & 1;
#pragma unroll
        for (int ks = 0; ks < 2; ks++) {
            const int kk = ks * 8;
            uint32_t a[4][4];
#pragma unroll
            for (int mt = 0; mt < 4; mt++) {
                const int r = wm + mt * 16 + qr;
                a[mt][0] = f2tf(As[s][r    ][kk + qc    ]);
                a[mt][1] = f2tf(As[s][r + 8][kk + qc    ]);
                a[mt][2] = f2tf(As[s][r    ][kk + qc + 4]);
                a[mt][3] = f2tf(As[s][r + 8][kk + qc + 4]);
            }
#pragma unroll
            for (int nt = 0; nt < 4; nt++) {
                const int nr = wn + nt * 8 + qr;
                uint32_t b0 = f2tf(Bs[s][nr][kk + qc    ]);
                uint32_t b1 = f2tf(Bs[s][nr][kk + qc + 4]);
#pragma unroll
                for (int mt = 0; mt < 4; mt++) mma_tf32(acc[mt][nt], a[mt], b0, b1);
            }
        }
        __syncthreads();
    }

    // epilogue: scatter to g_qkv[mat][win][h][t][d] with bias
    float* __restrict__ dstbase = g_qkv + (size_t)mat * MAT_ELEMS;
#pragma unroll
    for (int nt = 0; nt < 4; nt++) {
        const int col0 = wn + nt * 8 + 2 * qc;    // even
        const int nl   = nl0 + col0;
        const int h    = nl >> 6;
        const int d    = nl & 63;
        const float bv0 = bias[nl];
        const float bv1 = bias[nl + 1];
#pragma unroll
        for (int mt = 0; mt < 4; mt++) {
            const int m0  = bm0 + wm + mt * 16 + qr;
            // row a
            {
                const int win = m0 >> 6, t = m0 & 63;
                float2 v = make_float2(acc[mt][nt][0] + bv0, acc[mt][nt][1] + bv1);
                *(float2*)&dstbase[(((size_t)win * 8 + h) * 64 + t) * 64 + d] = v;
            }
            // row b (m0 + 8)
            {
                const int m1 = m0 + 8;
                const int win = m1 >> 6, t = m1 & 63;
                float2 v = make_float2(acc[mt][nt][2] + bv0, acc[mt][nt][3] + bv1);
                *(float2*)&dstbase[(((size_t)win * 8 + h) * 64 + t) * 64 + d] = v;
            }
        }
    }
}

// ---------------- Kernel 2: per-(window,head) attention ----------------
// CTA = (head, window). 128 threads = 4 warps, warp w owns q-rows [16w,16w+16)
#define PSTR 68   // smem row stride (floats), 16B-aligned

__global__ void __launch_bounds__(128)
attn_win(const float* __restrict__ Bbias, float* __restrict__ out)
{
    extern __shared__ float sm[];
    float* Qs = sm;                  // 64 x 68
    float* Ks = sm + 64 * PSTR;
    float* Vs = sm + 2 * 64 * PSTR;
    float* Ps = Qs;                  // reuse Q buffer for P (per-warp private rows)

    const int h   = blockIdx.x;
    const int win = blockIdx.y;
    const int tid = threadIdx.x;
    const int lane = tid & 31;
    const int warp = tid >> 5;
    const int qr = lane >> 2;        // 0..7
    const int qc = lane & 3;         // 0..3

    const size_t base = ((size_t)win * 8 + h) * 4096;
    const float* __restrict__ Qg = g_qkv + base;
    const float* __restrict__ Kg = g_qkv + (size_t)MAT_ELEMS + base;
    const float* __restrict__ Vg = g_qkv + 2u * (size_t)MAT_ELEMS + base;

    // stage Q,K,V (each 1024 float4; 8 per thread)
#pragma unroll
    for (int i = 0; i < 8; i++) {
        int idx = tid + i * 128;
        int r = idx >> 4, c4 = (idx & 15) * 4;
        *(float4*)&Qs[r * PSTR + c4] = *(const float4*)&Qg[idx * 4];
        *(float4*)&Ks[r * PSTR + c4] = *(const float4*)&Kg[idx * 4];
        *(float4*)&Vs[r * PSTR + c4] = *(const float4*)&Vg[idx * 4];
    }
    __syncthreads();

    const int r0 = warp * 16;

    // ---- S = Q K^T ----
    float acc[8][4];
#pragma unroll
    for (int nt = 0; nt < 8; nt++)
#pragma unroll
        for (int j = 0; j < 4; j++) acc[nt][j] = 0.f;

#pragma unroll
    for (int ks = 0; ks < 8; ks++) {
        const int kk = ks * 8;
        uint32_t a[4];
        a[0] = f2tf(Qs[(r0 + qr    ) * PSTR + kk + qc    ]);
        a[1] = f2tf(Qs[(r0 + qr + 8) * PSTR + kk + qc    ]);
        a[2] = f2tf(Qs[(r0 + qr    ) * PSTR + kk + qc + 4]);
        a[3] = f2tf(Qs[(r0 + qr + 8) * PSTR + kk + qc + 4]);
#pragma unroll
        for (int nt = 0; nt < 8; nt++) {
            uint32_t b0 = f2tf(Ks[(nt * 8 + qr) * PSTR + kk + qc    ]);
            uint32_t b1 = f2tf(Ks[(nt * 8 + qr) * PSTR + kk + qc + 4]);
            mma_tf32(acc[nt], a, b0, b1);
        }
    }

    // ---- scale + bias + softmax (rows ra = r0+qr, rb = ra+8) ----
    const int ra = r0 + qr, rb = ra + 8;
    const float scale = 0.125f;   // 1/sqrt(64)
    float mA = -1e30f, mB = -1e30f;
#pragma unroll
    for (int nt = 0; nt < 8; nt++) {
        const int col = nt * 8 + 2 * qc;
        acc[nt][0] = acc[nt][0] * scale + Bbias[ra * 64 + col];
        acc[nt][1] = acc[nt][1] * scale + Bbias[ra * 64 + col + 1];
        acc[nt][2] = acc[nt][2] * scale + Bbias[rb * 64 + col];
        acc[nt][3] = acc[nt][3] * scale + Bbias[rb * 64 + col + 1];
        mA = fmaxf(mA, fmaxf(acc[nt][0], acc[nt][1]));
        mB = fmaxf(mB, fmaxf(acc[nt][2], acc[nt][3]));
    }
    mA = fmaxf(mA, __shfl_xor_sync(0xffffffffu, mA, 1));
    mA = fmaxf(mA, __shfl_xor_sync(0xffffffffu, mA, 2));
    mB = fmaxf(mB, __shfl_xor_sync(0xffffffffu, mB, 1));
    mB = fmaxf(mB, __shfl_xor_sync(0xffffffffu, mB, 2));

    float sA = 0.f, sB = 0.f;
#pragma unroll
    for (int nt = 0; nt < 8; nt++) {
        acc[nt][0] = __expf(acc[nt][0] - mA);
        acc[nt][1] = __expf(acc[nt][1] - mA);
        acc[nt][2] = __expf(acc[nt][2] - mB);
        acc[nt][3] = __expf(acc[nt][3] - mB);
        sA += acc[nt][0] + acc[nt][1];
        sB += acc[nt][2] + acc[nt][3];
    }
    sA += __shfl_xor_sync(0xffffffffu, sA, 1);
    sA += __shfl_xor_sync(0xffffffffu, sA, 2);
    sB += __shfl_xor_sync(0xffffffffu, sB, 1);
    sB += __shfl_xor_sync(0xffffffffu, sB, 2);
    const float rA = 1.f / sA, rB = 1.f / sB;

#pragma unroll
    for (int nt = 0; nt < 8; nt++) {
        const int col = nt * 8 + 2 * qc;
        Ps[ra * PSTR + col    ] = acc[nt][0] * rA;
        Ps[ra * PSTR + col + 1] = acc[nt][1] * rA;
        Ps[rb * PSTR + col    ] = acc[nt][2] * rB;
        Ps[rb * PSTR + col + 1] = acc[nt][3] * rB;
    }
    __syncwarp();

    // ---- O = P V ----
    float o[8][4];
#pragma unroll
    for (int nt = 0; nt < 8; nt++)
#pragma unroll
        for (int j = 0; j < 4; j++) o[nt][j] = 0.f;

#pragma unroll
    for (int ks = 0; ks < 8; ks++) {
        const int kk = ks * 8;
        uint32_t a[4];
        a[0] = f2tf(Ps[(r0 + qr    ) * PSTR + kk + qc    ]);
        a[1] = f2tf(Ps[(r0 + qr + 8) * PSTR + kk + qc    ]);
        a[2] = f2tf(Ps[(r0 + qr    ) * PSTR + kk + qc + 4]);
        a[3] = f2tf(Ps[(r0 + qr + 8) * PSTR + kk + qc + 4]);
#pragma unroll
        for (int nt = 0; nt < 8; nt++) {
            uint32_t b0 = f2tf(Vs[(kk + qc    ) * PSTR + nt * 8 + qr]);
            uint32_t b1 = f2tf(Vs[(kk + qc + 4) * PSTR + nt * 8 + qr]);
            mma_tf32(o[nt], a, b0, b1);
        }
    }

    // ---- write output: out[(win*64 + t)*512 + h*64 + d] ----
    const size_t ob = (size_t)win * 64 * 512 + (size_t)h * 64;
#pragma unroll
    for (int nt = 0; nt < 8; nt++) {
        const int d0 = nt * 8 + 2 * qc;
        *(float2*)&out[ob + (size_t)ra * 512 + d0] = make_float2(o[nt][0], o[nt][1]);
        *(float2*)&out[ob + (size_t)rb * 512 + d0] = make_float2(o[nt][2], o[nt][3]);
    }
}

// ---------------- launcher ----------------
extern "C" void kernel_launch(void* const* d_in, const int* in_sizes, int n_in,
                              void* d_out, int out_size)
{
    const float* x    = (const float*)d_in[0];
    const float* Wq   = (const float*)d_in[1];
    const float* bq   = (const float*)d_in[2];
    const float* Wk   = (const float*)d_in[3];
    const float* bk   = (const float*)d_in[4];
    const float* Wv   = (const float*)d_in[5];
    const float* bv   = (const float*)d_in[6];
    const float* Bb   = (const float*)d_in[7];
    float* out = (float*)d_out;

    // Kernel 1: QKV projection GEMM (grid: N blocks x M blocks)
    dim3 g1(N_TOT / BN, M_TOK / BM);     // (12, 256)
    qkv_gemm<<<g1, 256>>>(x, Wq, bq, Wk, bk, Wv, bv);

    // Kernel 2: attention, one CTA per (head, window)
    static int smem_set = 0;
    const int smem_bytes = 3 * 64 * PSTR * sizeof(float);  // 52224
    cudaFuncSetAttribute(attn_win, cudaFuncAttributeMaxDynamicSharedMemorySize,
                         smem_bytes);
    (void)smem_set;
    dim3 g2(8, 512);
    attn_win<<<g2, 128, smem_bytes>>>(Bb, out);
}

// round 9
// speedup vs baseline: 1.2431x; 1.2431x over previous
#include <cuda_runtime.h>
#include <cuda_bf16.h>
#include <cstdint>

// Problem constants
#define M_TOK   32768          // B*NW*WIN tokens
#define C_DIM   512
#define MAT_ELEMS 16777216     // 512 windows * 8 heads * 64 tok * 64 d

// scratch
__device__ float g_qkv[3u * MAT_ELEMS];                 // Q,K,V in [win][h][t][d]
__device__ float g_xtf[(size_t)M_TOK * C_DIM];          // X pre-rounded to tf32
__device__ float g_wtf[3u * C_DIM * C_DIM];             // Wq,Wk,Wv pre-rounded to tf32

// ---------------- helpers ----------------
__device__ __forceinline__ uint32_t f2tf(float x) {
    uint32_t u;
    asm("cvt.rna.tf32.f32 %0, %1;" : "=r"(u) : "f"(x));
    return u;
}

__device__ __forceinline__ void mma_tf32(float c[4], const uint32_t a[4],
                                         uint32_t b0, uint32_t b1) {
    asm volatile(
        "mma.sync.aligned.m16n8k8.row.col.f32.tf32.tf32.f32 "
        "{%0,%1,%2,%3}, {%4,%5,%6,%7}, {%8,%9}, {%0,%1,%2,%3};"
        : "+f"(c[0]), "+f"(c[1]), "+f"(c[2]), "+f"(c[3])
        : "r"(a[0]), "r"(a[1]), "r"(a[2]), "r"(a[3]), "r"(b0), "r"(b1));
}

__device__ __forceinline__ void ldsm4(uint32_t (&d)[4], uint32_t addr) {
    asm volatile("ldmatrix.sync.aligned.m8n8.x4.shared.b16 {%0,%1,%2,%3}, [%4];"
                 : "=r"(d[0]), "=r"(d[1]), "=r"(d[2]), "=r"(d[3]) : "r"(addr));
}

__device__ __forceinline__ void cpa16(uint32_t s, const void* g) {
    asm volatile("cp.async.cg.shared.global [%0], [%1], 16;" :: "r"(s), "l"(g));
}

__device__ __forceinline__ uint32_t swz(uint32_t off) {   // SW128 byte swizzle
    return off ^ ((off >> 3) & 0x70);
}

// ---------------- Kernel 0: RNA pre-round to tf32 ----------------
__global__ void cvt_rna4(const float* __restrict__ src, float* __restrict__ dst, int n) {
    int i = (blockIdx.x * blockDim.x + threadIdx.x) * 4;
    int st = gridDim.x * blockDim.x * 4;
    for (; i < n; i += st) {
        float4 v = *(const float4*)(src + i);
        uint4 o;
        o.x = f2tf(v.x); o.y = f2tf(v.y); o.z = f2tf(v.z); o.w = f2tf(v.w);
        *(uint4*)(dst + i) = o;
    }
}

// ---------------- Kernel 1: QKV GEMM, tf32 mma + ldmatrix ----------------
// CTA tile 128x128, BK=32 (128B rows, SW128 swizzle), 2-stage cp.async.
// 8 warps: warp tile 64x32 (2x4 warp grid). No CVT in mainloop (pre-rounded data).
#define BM 128
#define BN 128
#define BK 32
#define A_STAGE 16384u            // bytes per A tile (128*32*4)
#define STAGE   32768u            // A+B per stage

__global__ void __launch_bounds__(256, 2)
qkv_gemm2(const float* __restrict__ bq, const float* __restrict__ bk,
          const float* __restrict__ bv)
{
    extern __shared__ char smraw[];
    const uint32_t base = ((uint32_t)__cvta_generic_to_shared(smraw) + 1023u) & ~1023u;

    const int tid  = threadIdx.x;
    const int lane = tid & 31;
    const int warp = tid >> 5;
    const int wm   = (warp >> 2) * 64;    // 0 or 64
    const int wn   = (warp & 3) * 32;     // 0,32,64,96

    const int bm0 = blockIdx.y * BM;
    const int bn0 = blockIdx.x * BN;
    const int mat = bn0 >> 9;             // 0,1,2
    const int nl0 = bn0 & 511;
    const float* __restrict__ W    = g_wtf + (size_t)mat * C_DIM * C_DIM;
    const float* __restrict__ bias = (mat == 0) ? bq : (mat == 1) ? bk : bv;

    float acc[4][4][4];
#pragma unroll
    for (int i = 0; i < 4; i++)
#pragma unroll
        for (int j = 0; j < 4; j++)
#pragma unroll
            for (int q = 0; q < 4; q++) acc[i][j][q] = 0.f;

    // per-thread ldmatrix base offsets (kb enters via XOR of bits 5-6)
    uint32_t aoff[4], boff[2];
    {
        const uint32_t acolb0 = ((lane >> 4) & 1) << 4;
#pragma unroll
        for (int mt = 0; mt < 4; mt++) {
            const uint32_t r = wm + mt * 16 + (lane & 15);
            aoff[mt] = swz(r * 128u + acolb0);
        }
        const uint32_t bcolb0 = ((lane >> 3) & 1) << 4;
        const uint32_t brow_l = ((lane & 16) >> 1) + (lane & 7);
#pragma unroll
        for (int p = 0; p < 2; p++) {
            const uint32_t r = wn + p * 16 + brow_l;
            boff[p] = swz(r * 128u + bcolb0);
        }
    }

    // stage loader: 1024 16B chunks each for A and B; 4+4 per thread
    auto loadc = [&](int c) {
        const uint32_t a_st = base + (uint32_t)(c & 1) * STAGE;
        const uint32_t b_st = a_st + A_STAGE;
        const int k0 = c * BK;
#pragma unroll
        for (int i = 0; i < 4; i++) {
            const int idx = tid + i * 256;
            const int r = idx >> 3, c16 = idx & 7;
            const uint32_t sw = swz((uint32_t)(r * 128 + c16 * 16));
            cpa16(a_st + sw, g_xtf + (size_t)(bm0 + r) * C_DIM + k0 + c16 * 4);
            cpa16(b_st + sw, W     + (size_t)(nl0 + r) * C_DIM + k0 + c16 * 4);
        }
        asm volatile("cp.async.commit_group;" ::: "memory");
    };

    loadc(0);

    const int NC = C_DIM / BK;   // 16
    for (int c = 0; c < NC; c++) {
        if (c + 1 < NC) {
            loadc(c + 1);
            asm volatile("cp.async.wait_group 1;" ::: "memory");
        } else {
            asm volatile("cp.async.wait_group 0;" ::: "memory");
        }
        __syncthreads();

        const uint32_t a_st = base + (uint32_t)(c & 1) * STAGE;
        const uint32_t b_st = a_st + A_STAGE;
#pragma unroll
        for (int kb = 0; kb < 4; kb++) {
            const uint32_t kx = (uint32_t)kb << 5;
            uint32_t a[4][4];
#pragma unroll
            for (int mt = 0; mt < 4; mt++) ldsm4(a[mt], a_st + (aoff[mt] ^ kx));
            uint32_t b0r[4], b1r[4];
            ldsm4(b0r, b_st + (boff[0] ^ kx));
            ldsm4(b1r, b_st + (boff[1] ^ kx));
#pragma unroll
            for (int mt = 0; mt < 4; mt++) {
                mma_tf32(acc[mt][0], a[mt], b0r[0], b0r[1]);
                mma_tf32(acc[mt][1], a[mt], b0r[2], b0r[3]);
                mma_tf32(acc[mt][2], a[mt], b1r[0], b1r[1]);
                mma_tf32(acc[mt][3], a[mt], b1r[2], b1r[3]);
            }
        }
        __syncthreads();
    }

    // epilogue: scatter to g_qkv[mat][win][h][t][d] with bias (layout verified in R1)
    const int qr = lane >> 2, qc = lane & 3;
    float* __restrict__ dstb = g_qkv + (size_t)mat * MAT_ELEMS;
#pragma unroll
    for (int nt = 0; nt < 4; nt++) {
        const int col0 = wn + nt * 8 + 2 * qc;
        const int nl   = nl0 + col0;
        const int h    = nl >> 6;
        const int d    = nl & 63;
        const float bv0 = bias[nl];
        const float bv1 = bias[nl + 1];
#pragma unroll
        for (int mt = 0; mt < 4; mt++) {
            const int m0 = bm0 + wm + mt * 16 + qr;
            {
                const int win = m0 >> 6, t = m0 & 63;
                float2 v = make_float2(acc[mt][nt][0] + bv0, acc[mt][nt][1] + bv1);
                *(float2*)&dstb[(((size_t)win * 8 + h) * 64 + t) * 64 + d] = v;
            }
            {
                const int m1 = m0 + 8;
                const int win = m1 >> 6, t = m1 & 63;
                float2 v = make_float2(acc[mt][nt][2] + bv0, acc[mt][nt][3] + bv1);
                *(float2*)&dstb[(((size_t)win * 8 + h) * 64 + t) * 64 + d] = v;
            }
        }
    }
}

// ---------------- Kernel 2: per-(window,head) attention (unchanged, measured 83us) ----------------
#define PSTR 68

__global__ void __launch_bounds__(128)
attn_win(const float* __restrict__ Bbias, float* __restrict__ out)
{
    extern __shared__ float sm[];
    float* Qs = sm;
    float* Ks = sm + 64 * PSTR;
    float* Vs = sm + 2 * 64 * PSTR;
    float* Ps = Qs;

    const int h   = blockIdx.x;
    const int win = blockIdx.y;
    const int tid = threadIdx.x;
    const int lane = tid & 31;
    const int warp = tid >> 5;
    const int qr = lane >> 2;
    const int qc = lane & 3;

    const size_t base = ((size_t)win * 8 + h) * 4096;
    const float* __restrict__ Qg = g_qkv + base;
    const float* __restrict__ Kg = g_qkv + (size_t)MAT_ELEMS + base;
    const float* __restrict__ Vg = g_qkv + 2u * (size_t)MAT_ELEMS + base;

#pragma unroll
    for (int i = 0; i < 8; i++) {
        int idx = tid + i * 128;
        int r = idx >> 4, c4 = (idx & 15) * 4;
        *(float4*)&Qs[r * PSTR + c4] = *(const float4*)&Qg[idx * 4];
        *(float4*)&Ks[r * PSTR + c4] = *(const float4*)&Kg[idx * 4];
        *(float4*)&Vs[r * PSTR + c4] = *(const float4*)&Vg[idx * 4];
    }
    __syncthreads();

    const int r0 = warp * 16;

    float acc[8][4];
#pragma unroll
    for (int nt = 0; nt < 8; nt++)
#pragma unroll
        for (int j = 0; j < 4; j++) acc[nt][j] = 0.f;

#pragma unroll
    for (int ks = 0; ks < 8; ks++) {
        const int kk = ks * 8;
        uint32_t a[4];
        a[0] = f2tf(Qs[(r0 + qr    ) * PSTR + kk + qc    ]);
        a[1] = f2tf(Qs[(r0 + qr + 8) * PSTR + kk + qc    ]);
        a[2] = f2tf(Qs[(r0 + qr    ) * PSTR + kk + qc + 4]);
        a[3] = f2tf(Qs[(r0 + qr + 8) * PSTR + kk + qc + 4]);
#pragma unroll
        for (int nt = 0; nt < 8; nt++) {
            uint32_t b0 = f2tf(Ks[(nt * 8 + qr) * PSTR + kk + qc    ]);
            uint32_t b1 = f2tf(Ks[(nt * 8 + qr) * PSTR + kk + qc + 4]);
            mma_tf32(acc[nt], a, b0, b1);
        }
    }

    const int ra = r0 + qr, rb = ra + 8;
    const float scale = 0.125f;
    float mA = -1e30f, mB = -1e30f;
#pragma unroll
    for (int nt = 0; nt < 8; nt++) {
        const int col = nt * 8 + 2 * qc;
        acc[nt][0] = acc[nt][0] * scale + Bbias[ra * 64 + col];
        acc[nt][1] = acc[nt][1] * scale + Bbias[ra * 64 + col + 1];
        acc[nt][2] = acc[nt][2] * scale + Bbias[rb * 64 + col];
        acc[nt][3] = acc[nt][3] * scale + Bbias[rb * 64 + col + 1];
        mA = fmaxf(mA, fmaxf(acc[nt][0], acc[nt][1]));
        mB = fmaxf(mB, fmaxf(acc[nt][2], acc[nt][3]));
    }
    mA = fmaxf(mA, __shfl_xor_sync(0xffffffffu, mA, 1));
    mA = fmaxf(mA, __shfl_xor_sync(0xffffffffu, mA, 2));
    mB = fmaxf(mB, __shfl_xor_sync(0xffffffffu, mB, 1));
    mB = fmaxf(mB, __shfl_xor_sync(0xffffffffu, mB, 2));

    float sA = 0.f, sB = 0.f;
#pragma unroll
    for (int nt = 0; nt < 8; nt++) {
        acc[nt][0] = __expf(acc[nt][0] - mA);
        acc[nt][1] = __expf(acc[nt][1] - mA);
        acc[nt][2] = __expf(acc[nt][2] - mB);
        acc[nt][3] = __expf(acc[nt][3] - mB);
        sA += acc[nt][0] + acc[nt][1];
        sB += acc[nt][2] + acc[nt][3];
    }
    sA += __shfl_xor_sync(0xffffffffu, sA, 1);
    sA += __shfl_xor_sync(0xffffffffu, sA, 2);
    sB += __shfl_xor_sync(0xffffffffu, sB, 1);
    sB += __shfl_xor_sync(0xffffffffu, sB, 2);
    const float rA = 1.f / sA, rB = 1.f / sB;

#pragma unroll
    for (int nt = 0; nt < 8; nt++) {
        const int col = nt * 8 + 2 * qc;
        Ps[ra * PSTR + col    ] = acc[nt][0] * rA;
        Ps[ra * PSTR + col + 1] = acc[nt][1] * rA;
        Ps[rb * PSTR + col    ] = acc[nt][2] * rB;
        Ps[rb * PSTR + col + 1] = acc[nt][3] * rB;
    }
    __syncwarp();

    float o[8][4];
#pragma unroll
    for (int nt = 0; nt < 8; nt++)
#pragma unroll
        for (int j = 0; j < 4; j++) o[nt][j] = 0.f;

#pragma unroll
    for (int ks = 0; ks < 8; ks++) {
        const int kk = ks * 8;
        uint32_t a[4];
        a[0] = f2tf(Ps[(r0 + qr    ) * PSTR + kk + qc    ]);
        a[1] = f2tf(Ps[(r0 + qr + 8) * PSTR + kk + qc    ]);
        a[2] = f2tf(Ps[(r0 + qr    ) * PSTR + kk + qc + 4]);
        a[3] = f2tf(Ps[(r0 + qr + 8) * PSTR + kk + qc + 4]);
#pragma unroll
        for (int nt = 0; nt < 8; nt++) {
            uint32_t b0 = f2tf(Vs[(kk + qc    ) * PSTR + nt * 8 + qr]);
            uint32_t b1 = f2tf(Vs[(kk + qc + 4) * PSTR + nt * 8 + qr]);
            mma_tf32(o[nt], a, b0, b1);
        }
    }

    const size_t ob = (size_t)win * 64 * 512 + (size_t)h * 64;
#pragma unroll
    for (int nt = 0; nt < 8; nt++) {
        const int d0 = nt * 8 + 2 * qc;
        *(float2*)&out[ob + (size_t)ra * 512 + d0] = make_float2(o[nt][0], o[nt][1]);
        *(float2*)&out[ob + (size_t)rb * 512 + d0] = make_float2(o[nt][2], o[nt][3]);
    }
}

// ---------------- launcher ----------------
extern "C" void kernel_launch(void* const* d_in, const int* in_sizes, int n_in,
                              void* d_out, int out_size)
{
    const float* x    = (const float*)d_in[0];
    const float* Wq   = (const float*)d_in[1];
    const float* bq   = (const float*)d_in[2];
    const float* Wk   = (const float*)d_in[3];
    const float* bk   = (const float*)d_in[4];
    const float* Wv   = (const float*)d_in[5];
    const float* bv   = (const float*)d_in[6];
    const float* Bb   = (const float*)d_in[7];
    float* out = (float*)d_out;

    float* xtf = nullptr;
    float* wtf = nullptr;
    cudaGetSymbolAddress((void**)&xtf, g_xtf);
    cudaGetSymbolAddress((void**)&wtf, g_wtf);

    // Kernel 0: RNA round X and W to tf32 (kills in-loop CVT, preserves accuracy)
    cvt_rna4<<<1024, 256>>>(x, xtf, M_TOK * C_DIM);
    cvt_rna4<<<128, 256>>>(Wq, wtf, C_DIM * C_DIM);
    cvt_rna4<<<128, 256>>>(Wk, wtf + C_DIM * C_DIM, C_DIM * C_DIM);
    cvt_rna4<<<128, 256>>>(Wv, wtf + 2 * C_DIM * C_DIM, C_DIM * C_DIM);

    // Kernel 1: QKV GEMM (ldmatrix + tf32 mma)
    const int smem1 = 2 * STAGE + 1024;   // 66560
    cudaFuncSetAttribute(qkv_gemm2, cudaFuncAttributeMaxDynamicSharedMemorySize, smem1);
    dim3 g1(12, 256);
    qkv_gemm2<<<g1, 256, smem1>>>(bq, bk, bv);

    // Kernel 2: attention
    const int smem2 = 3 * 64 * PSTR * sizeof(float);
    cudaFuncSetAttribute(attn_win, cudaFuncAttributeMaxDynamicSharedMemorySize, smem2);
    dim3 g2(8, 512);
    attn_win<<<g2, 128, smem2>>>(Bb, out);
}